// round 4
// baseline (speedup 1.0000x reference)
#include <cuda_runtime.h>

namespace {

constexpr int BATCH   = 4;
constexpr int NIN     = 1024;
constexpr int NOUT    = 1024;
constexpr int CH      = 8;     // density + 7 raw channels
constexpr int OC      = 16;
constexpr int OPB     = 32;    // outputs per block (= warp width)
constexpr int SPLITS  = 8;     // i-dimension splits across blocks
constexpr int ISPB    = NIN / SPLITS;      // 128 i per block
constexpr int THREADS = 256;
constexpr int WARPS   = THREADS / 32;      // 8
constexpr int IPW     = ISPB / WARPS;      // 16 i per warp

// Partial aggregates: [b*1024+O][split][c]  (1 MB scratch)
__device__ float g_part[BATCH * NOUT * SPLITS * CH];

__device__ __forceinline__ float ex2_approx(float x) {
    float y;
    asm("ex2.approx.f32 %0, %1;" : "=f"(y) : "f"(x));
    return y;
}

// ---------------- Kernel A: partial aggregation over an i-slice ----------
__global__ __launch_bounds__(THREADS, 6)
void agg_kernel(const float* __restrict__ cx,     // [B, NIN, 1]
                const float* __restrict__ cy,     // [B, NIN, 7]
                const float* __restrict__ t,      // [B, NOUT, 1]
                const float* __restrict__ sigma)  // [8]
{
    __shared__ float4 sxy[ISPB][2];              // 4 KB packed {x,y1..y3},{y4..y7}
    __shared__ float  spart[WARPS][OPB][CH];     // 8 KB
    __shared__ float  sbeta[CH];

    const int bi    = blockIdx.x;
    const int b     = bi >> 8;                   // / (32*8)
    const int otile = (bi >> 3) & 31;
    const int split = bi & 7;
    const int tid   = threadIdx.x;
    const int warp  = tid >> 5;
    const int lane  = tid & 31;
    const int i0    = split * ISPB;

    if (tid < CH) {
        float s = expf(sigma[tid]);
        sbeta[tid] = -0.5f * 1.4426950408889634f / (s * s);
    }

    // Stage the 128-row slice: 4 iterations per thread
    {
        float* s = reinterpret_cast<float*>(sxy);
        #pragma unroll
        for (int r = 0; r < 4; r++) {
            int idx = tid + r * THREADS;         // 0..1023
            int i = idx >> 3, c = idx & 7;
            s[idx] = (c == 0) ? cx[b * NIN + i0 + i]
                              : cy[(b * NIN + i0 + i) * 7 + (c - 1)];
        }
    }

    const float t_o = t[b * NOUT + otile * OPB + lane];
    __syncthreads();

    const float beta0 = sbeta[0];
    bool uni = true;
    #pragma unroll
    for (int c = 1; c < CH; c++) uni &= (sbeta[c] == beta0);

    float acc[CH];
    #pragma unroll
    for (int c = 0; c < CH; c++) acc[c] = 0.0f;

    const float4* row = &sxy[warp * IPW][0];

    if (uni) {
        #pragma unroll
        for (int j = 0; j < IPW; j++) {
            float4 p0 = row[2 * j];              // broadcast LDS.128
            float4 p1 = row[2 * j + 1];
            float d = p0.x - t_o;
            float w = ex2_approx(beta0 * (d * d));
            acc[0] += w;                         // density channel: y == 1
            acc[1] += p0.y * w;  acc[2] += p0.z * w;  acc[3] += p0.w * w;
            acc[4] += p1.x * w;  acc[5] += p1.y * w;
            acc[6] += p1.z * w;  acc[7] += p1.w * w;
        }
    } else {
        #pragma unroll 4
        for (int j = 0; j < IPW; j++) {
            float4 p0 = row[2 * j];
            float4 p1 = row[2 * j + 1];
            float d = p0.x - t_o;
            float u = d * d;
            acc[0] += ex2_approx(sbeta[0] * u);
            acc[1] += p0.y * ex2_approx(sbeta[1] * u);
            acc[2] += p0.z * ex2_approx(sbeta[2] * u);
            acc[3] += p0.w * ex2_approx(sbeta[3] * u);
            acc[4] += p1.x * ex2_approx(sbeta[4] * u);
            acc[5] += p1.y * ex2_approx(sbeta[5] * u);
            acc[6] += p1.z * ex2_approx(sbeta[6] * u);
            acc[7] += p1.w * ex2_approx(sbeta[7] * u);
        }
    }

    // Per-warp partials
    *reinterpret_cast<float4*>(&spart[warp][lane][0]) =
        make_float4(acc[0], acc[1], acc[2], acc[3]);
    *reinterpret_cast<float4*>(&spart[warp][lane][4]) =
        make_float4(acc[4], acc[5], acc[6], acc[7]);
    __syncthreads();

    // Cross-warp reduce: one thread per (o, c); write partial to scratch
    {
        int o = tid >> 3, c = tid & 7;
        float s = 0.0f;
        #pragma unroll
        for (int w2 = 0; w2 < WARPS; w2++) s += spart[w2][o][c];
        int G = b * NOUT + otile * OPB + o;
        g_part[(G * SPLITS + split) * CH + c] = s;
    }
}

// ---------------- Kernel B: combine splits + normalize + linear ----------
constexpr int OPB_B = 128;   // outputs per block -> grid 32

__global__ __launch_bounds__(256)
void finish_kernel(const float* __restrict__ W,     // [8, 16]
                   const float* __restrict__ bias,  // [16]
                   float* __restrict__ out)         // [B*NOUT, 16]
{
    __shared__ float sagg [OPB_B][CH];
    __shared__ float sagg2[OPB_B][CH];

    const int tid = threadIdx.x;
    const int G0  = blockIdx.x * OPB_B;

    // Phase 1: sum 8 splits. thread -> (o_l, quad): 128*2 = 256 slots
    {
        int o_l = tid >> 1, q = tid & 1;
        const float4* p = reinterpret_cast<const float4*>(
            &g_part[((G0 + o_l) * SPLITS) * CH + q * 4]);
        float4 s = make_float4(0.f, 0.f, 0.f, 0.f);
        #pragma unroll
        for (int sp = 0; sp < SPLITS; sp++) {
            float4 v = p[sp * 2];                // stride 8 floats = 2 float4
            s.x += v.x; s.y += v.y; s.z += v.z; s.w += v.w;
        }
        *reinterpret_cast<float4*>(&sagg[o_l][q * 4]) = s;
    }
    __syncthreads();

    // Phase 2: normalize
    #pragma unroll
    for (int r = 0; r < 4; r++) {
        int idx = tid + r * 256;                 // 0..1023
        int o_l = idx >> 3, c = idx & 7;
        float den = sagg[o_l][0];
        float v = sagg[o_l][c];
        sagg2[o_l][c] = (c == 0) ? den : v / (den + 1e-8f);
    }
    __syncthreads();

    // Phase 3: out[G][k] = bias[k] + sum_c agg2[c] * W[c][k]
    #pragma unroll
    for (int r = 0; r < 8; r++) {
        int idx = tid + r * 256;                 // 0..2047
        int o_l = idx >> 4, k = idx & 15;
        float v = __ldg(&bias[k]);
        #pragma unroll
        for (int c = 0; c < CH; c++) v += sagg2[o_l][c] * __ldg(&W[c * OC + k]);
        out[(G0 + o_l) * OC + k] = v;
    }
}

} // namespace

extern "C" void kernel_launch(void* const* d_in, const int* in_sizes, int n_in,
                              void* d_out, int out_size) {
    const float* cx = (const float*)d_in[0];  // context_x
    const float* cy = (const float*)d_in[1];  // context_y
    const float* t  = (const float*)d_in[2];  // t
    const float* sg = (const float*)d_in[3];  // sigma
    const float* W  = (const float*)d_in[4];  // W
    const float* bi = (const float*)d_in[5];  // b
    float* out = (float*)d_out;

    agg_kernel<<<BATCH * 32 * SPLITS, THREADS>>>(cx, cy, t, sg);   // 1024 blocks
    finish_kernel<<<BATCH * NOUT / OPB_B, 256>>>(W, bi, out);      // 32 blocks
}

// round 5
// speedup vs baseline: 1.0363x; 1.0363x over previous
#include <cuda_runtime.h>

namespace {

constexpr int BATCH   = 4;
constexpr int NIN     = 1024;
constexpr int NOUT    = 1024;
constexpr int CH      = 8;     // density + 7 raw channels
constexpr int OC      = 16;
constexpr int OPB     = 32;    // outputs per block (= warp width)
constexpr int SPLITS  = 8;     // i-dimension splits across blocks
constexpr int ISPB    = NIN / SPLITS;      // 128 i per block
constexpr int THREADS = 256;
constexpr int WARPS   = THREADS / 32;      // 8
constexpr int IPW     = ISPB / WARPS;      // 16 i per warp

// Partial aggregates: [b*1024+O][split][c]  (1 MB scratch)
__device__ float g_part[BATCH * NOUT * SPLITS * CH];

__device__ __forceinline__ float ex2_approx(float x) {
    float y;
    asm("ex2.approx.f32 %0, %1;" : "=f"(y) : "f"(x));
    return y;
}

// ---------------- Kernel A: partial aggregation over an i-slice ----------
__global__ __launch_bounds__(THREADS, 6)
void agg_kernel(const float* __restrict__ cx,     // [B, NIN, 1]
                const float* __restrict__ cy,     // [B, NIN, 7]
                const float* __restrict__ t,      // [B, NOUT, 1]
                const float* __restrict__ sigma)  // [8]
{
    __shared__ float4 sxy[ISPB][2];              // 4 KB packed {x,y1..y3},{y4..y7}
    __shared__ float  spart[WARPS][OPB][CH];     // 8 KB
    __shared__ float  sbeta[CH];

    const int bi    = blockIdx.x;
    const int b     = bi >> 8;                   // / (32*8)
    const int otile = (bi >> 3) & 31;
    const int split = bi & 7;
    const int tid   = threadIdx.x;
    const int warp  = tid >> 5;
    const int lane  = tid & 31;
    const int i0    = split * ISPB;

    if (tid < CH) {
        float s = expf(sigma[tid]);
        sbeta[tid] = -0.5f * 1.4426950408889634f / (s * s);
    }

    // Stage the 128-row slice: 4 iterations per thread
    {
        float* s = reinterpret_cast<float*>(sxy);
        #pragma unroll
        for (int r = 0; r < 4; r++) {
            int idx = tid + r * THREADS;         // 0..1023
            int i = idx >> 3, c = idx & 7;
            s[idx] = (c == 0) ? cx[b * NIN + i0 + i]
                              : cy[(b * NIN + i0 + i) * 7 + (c - 1)];
        }
    }

    const float t_o = t[b * NOUT + otile * OPB + lane];
    __syncthreads();

    const float beta0 = sbeta[0];
    bool uni = true;
    #pragma unroll
    for (int c = 1; c < CH; c++) uni &= (sbeta[c] == beta0);

    float acc[CH];
    #pragma unroll
    for (int c = 0; c < CH; c++) acc[c] = 0.0f;

    const float4* row = &sxy[warp * IPW][0];

    if (uni) {
        #pragma unroll
        for (int j = 0; j < IPW; j++) {
            float4 p0 = row[2 * j];              // broadcast LDS.128
            float4 p1 = row[2 * j + 1];
            float d = p0.x - t_o;
            float w = ex2_approx(beta0 * (d * d));
            acc[0] += w;                         // density channel: y == 1
            acc[1] += p0.y * w;  acc[2] += p0.z * w;  acc[3] += p0.w * w;
            acc[4] += p1.x * w;  acc[5] += p1.y * w;
            acc[6] += p1.z * w;  acc[7] += p1.w * w;
        }
    } else {
        #pragma unroll 4
        for (int j = 0; j < IPW; j++) {
            float4 p0 = row[2 * j];
            float4 p1 = row[2 * j + 1];
            float d = p0.x - t_o;
            float u = d * d;
            acc[0] += ex2_approx(sbeta[0] * u);
            acc[1] += p0.y * ex2_approx(sbeta[1] * u);
            acc[2] += p0.z * ex2_approx(sbeta[2] * u);
            acc[3] += p0.w * ex2_approx(sbeta[3] * u);
            acc[4] += p1.x * ex2_approx(sbeta[4] * u);
            acc[5] += p1.y * ex2_approx(sbeta[5] * u);
            acc[6] += p1.z * ex2_approx(sbeta[6] * u);
            acc[7] += p1.w * ex2_approx(sbeta[7] * u);
        }
    }

    // Per-warp partials
    *reinterpret_cast<float4*>(&spart[warp][lane][0]) =
        make_float4(acc[0], acc[1], acc[2], acc[3]);
    *reinterpret_cast<float4*>(&spart[warp][lane][4]) =
        make_float4(acc[4], acc[5], acc[6], acc[7]);
    __syncthreads();

    // Cross-warp reduce: one thread per (o, c); write partial to scratch
    {
        int o = tid >> 3, c = tid & 7;
        float s = 0.0f;
        #pragma unroll
        for (int w2 = 0; w2 < WARPS; w2++) s += spart[w2][o][c];
        int G = b * NOUT + otile * OPB + o;
        g_part[(G * SPLITS + split) * CH + c] = s;
    }
}

// ---------------- Kernel B: combine splits + normalize + linear ----------
// 256 blocks x 128 threads; 16 outputs per block.
constexpr int OPB_B   = 16;
constexpr int THREADS_B = 128;

__global__ __launch_bounds__(THREADS_B)
void finish_kernel(const float* __restrict__ W,     // [8, 16]
                   const float* __restrict__ bias,  // [16]
                   float* __restrict__ out)         // [B*NOUT, 16]
{
    __shared__ float sagg2[OPB_B][CH];               // 512 B

    const int tid  = threadIdx.x;
    const int lane = tid & 31;
    const int G0   = blockIdx.x * OPB_B;

    // Phase 1: one thread per (o_l, c); 8 independent LDG (MLP=8), all L2 hits
    {
        int o_l = tid >> 3, c = tid & 7;             // 16 x 8 = 128 threads
        const float* p = &g_part[((G0 + o_l) * SPLITS) * CH + c];
        float s = 0.0f;
        #pragma unroll
        for (int sp = 0; sp < SPLITS; sp++) s += p[sp * CH];
        // den for this o_l sits in the c==0 lane of the same group of 8
        float den = __shfl_sync(0xffffffffu, s, lane & ~7u);
        sagg2[o_l][c] = (c == 0) ? s : s / (den + 1e-8f);
    }
    __syncthreads();

    // Phase 2: out[G][k] = bias[k] + sum_c agg2[c] * W[c][k]
    #pragma unroll
    for (int r = 0; r < 2; r++) {
        int idx = tid + r * THREADS_B;               // 0..255
        int o_l = idx >> 4, k = idx & 15;
        float v = __ldg(&bias[k]);
        #pragma unroll
        for (int c = 0; c < CH; c++) v += sagg2[o_l][c] * __ldg(&W[c * OC + k]);
        out[(G0 + o_l) * OC + k] = v;                // fully coalesced
    }
}

} // namespace

extern "C" void kernel_launch(void* const* d_in, const int* in_sizes, int n_in,
                              void* d_out, int out_size) {
    const float* cx = (const float*)d_in[0];  // context_x
    const float* cy = (const float*)d_in[1];  // context_y
    const float* t  = (const float*)d_in[2];  // t
    const float* sg = (const float*)d_in[3];  // sigma
    const float* W  = (const float*)d_in[4];  // W
    const float* bi = (const float*)d_in[5];  // b
    float* out = (float*)d_out;

    agg_kernel<<<BATCH * 32 * SPLITS, THREADS>>>(cx, cy, t, sg);        // 1024 blocks
    finish_kernel<<<BATCH * NOUT / OPB_B, THREADS_B>>>(W, bi, out);     // 256 blocks
}

// round 6
// speedup vs baseline: 1.1364x; 1.0966x over previous
#include <cuda_runtime.h>

namespace {

constexpr int BATCH   = 4;
constexpr int NIN     = 1024;
constexpr int NOUT    = 1024;
constexpr int CH      = 8;     // density + 7 raw channels
constexpr int OC      = 16;
constexpr int OPB     = 32;    // outputs per block (= warp width)
constexpr int SPLITS  = 4;     // i-dimension splits across blocks
constexpr int ISPB    = NIN / SPLITS;      // 256 i per block
constexpr int THREADS = 256;
constexpr int WARPS   = THREADS / 32;      // 8
constexpr int IPW     = ISPB / WARPS;      // 32 i per warp

// Partial aggregates: [b*1024+O][split][c]  (512 KB scratch)
__device__ float g_part[BATCH * NOUT * SPLITS * CH];

__device__ __forceinline__ float ex2_approx(float x) {
    float y;
    asm("ex2.approx.f32 %0, %1;" : "=f"(y) : "f"(x));
    return y;
}

// ---------------- Kernel A: partial aggregation over an i-slice ----------
// launch_bounds(256, 4): 64-reg budget -> no spills (R2-validated), 32 warps/SM.
__global__ __launch_bounds__(THREADS, 4)
void agg_kernel(const float* __restrict__ cx,     // [B, NIN, 1]
                const float* __restrict__ cy,     // [B, NIN, 7]
                const float* __restrict__ t,      // [B, NOUT, 1]
                const float* __restrict__ sigma)  // [8]
{
    __shared__ float4 sxy[ISPB][2];              // 8 KB packed {x,y1..y3},{y4..y7}
    __shared__ float  spart[WARPS][OPB][CH];     // 8 KB
    __shared__ float  sbeta[CH];

    const int bi    = blockIdx.x;
    const int b     = bi >> 7;                   // / (32*4)
    const int otile = (bi >> 2) & 31;
    const int split = bi & 3;
    const int tid   = threadIdx.x;
    const int warp  = tid >> 5;
    const int lane  = tid & 31;
    const int i0    = split * ISPB;

    if (tid < CH) {
        float s = expf(sigma[tid]);
        sbeta[tid] = -0.5f * 1.4426950408889634f / (s * s);
    }

    // Stage the 256-row slice: 8 iterations per thread
    {
        float* s = reinterpret_cast<float*>(sxy);
        #pragma unroll
        for (int r = 0; r < 8; r++) {
            int idx = tid + r * THREADS;         // 0..2047
            int i = idx >> 3, c = idx & 7;
            s[idx] = (c == 0) ? cx[b * NIN + i0 + i]
                              : cy[(b * NIN + i0 + i) * 7 + (c - 1)];
        }
    }

    const float t_o = t[b * NOUT + otile * OPB + lane];
    __syncthreads();

    const float beta0 = sbeta[0];
    bool uni = true;
    #pragma unroll
    for (int c = 1; c < CH; c++) uni &= (sbeta[c] == beta0);

    float acc[CH];
    #pragma unroll
    for (int c = 0; c < CH; c++) acc[c] = 0.0f;

    const float4* row = &sxy[warp * IPW][0];

    if (uni) {
        #pragma unroll 8
        for (int j = 0; j < IPW; j++) {
            float4 p0 = row[2 * j];              // broadcast LDS.128
            float4 p1 = row[2 * j + 1];
            float d = p0.x - t_o;
            float w = ex2_approx(beta0 * (d * d));
            acc[0] += w;                         // density channel: y == 1
            acc[1] += p0.y * w;  acc[2] += p0.z * w;  acc[3] += p0.w * w;
            acc[4] += p1.x * w;  acc[5] += p1.y * w;
            acc[6] += p1.z * w;  acc[7] += p1.w * w;
        }
    } else {
        #pragma unroll 4
        for (int j = 0; j < IPW; j++) {
            float4 p0 = row[2 * j];
            float4 p1 = row[2 * j + 1];
            float d = p0.x - t_o;
            float u = d * d;
            acc[0] += ex2_approx(sbeta[0] * u);
            acc[1] += p0.y * ex2_approx(sbeta[1] * u);
            acc[2] += p0.z * ex2_approx(sbeta[2] * u);
            acc[3] += p0.w * ex2_approx(sbeta[3] * u);
            acc[4] += p1.x * ex2_approx(sbeta[4] * u);
            acc[5] += p1.y * ex2_approx(sbeta[5] * u);
            acc[6] += p1.z * ex2_approx(sbeta[6] * u);
            acc[7] += p1.w * ex2_approx(sbeta[7] * u);
        }
    }

    // Per-warp partials
    *reinterpret_cast<float4*>(&spart[warp][lane][0]) =
        make_float4(acc[0], acc[1], acc[2], acc[3]);
    *reinterpret_cast<float4*>(&spart[warp][lane][4]) =
        make_float4(acc[4], acc[5], acc[6], acc[7]);
    __syncthreads();

    // Cross-warp reduce: one thread per (o, c); write partial to scratch
    {
        int o = tid >> 3, c = tid & 7;
        float s = 0.0f;
        #pragma unroll
        for (int w2 = 0; w2 < WARPS; w2++) s += spart[w2][o][c];
        int G = b * NOUT + otile * OPB + o;
        g_part[(G * SPLITS + split) * CH + c] = s;
    }
}

// ---------------- Kernel B: combine splits + normalize + linear ----------
// 256 blocks x 128 threads; 16 outputs per block.
constexpr int OPB_B     = 16;
constexpr int THREADS_B = 128;

__global__ __launch_bounds__(THREADS_B)
void finish_kernel(const float* __restrict__ W,     // [8, 16]
                   const float* __restrict__ bias,  // [16]
                   float* __restrict__ out)         // [B*NOUT, 16]
{
    __shared__ float sagg2[OPB_B][CH];               // 512 B

    const int tid  = threadIdx.x;
    const int lane = tid & 31;
    const int G0   = blockIdx.x * OPB_B;

    // Phase 1: one thread per (o_l, c); 4 independent LDG (L2 hits in timed run)
    {
        int o_l = tid >> 3, c = tid & 7;             // 16 x 8 = 128 threads
        const float* p = &g_part[((G0 + o_l) * SPLITS) * CH + c];
        float s = 0.0f;
        #pragma unroll
        for (int sp = 0; sp < SPLITS; sp++) s += p[sp * CH];
        // den for this o_l sits in the c==0 lane of the same group of 8
        float den = __shfl_sync(0xffffffffu, s, lane & ~7u);
        sagg2[o_l][c] = (c == 0) ? s : s / (den + 1e-8f);
    }
    __syncthreads();

    // Phase 2: out[G][k] = bias[k] + sum_c agg2[c] * W[c][k]
    #pragma unroll
    for (int r = 0; r < 2; r++) {
        int idx = tid + r * THREADS_B;               // 0..255
        int o_l = idx >> 4, k = idx & 15;
        float v = __ldg(&bias[k]);
        #pragma unroll
        for (int c = 0; c < CH; c++) v += sagg2[o_l][c] * __ldg(&W[c * OC + k]);
        out[(G0 + o_l) * OC + k] = v;                // fully coalesced
    }
}

} // namespace

extern "C" void kernel_launch(void* const* d_in, const int* in_sizes, int n_in,
                              void* d_out, int out_size) {
    const float* cx = (const float*)d_in[0];  // context_x
    const float* cy = (const float*)d_in[1];  // context_y
    const float* t  = (const float*)d_in[2];  // t
    const float* sg = (const float*)d_in[3];  // sigma
    const float* W  = (const float*)d_in[4];  // W
    const float* bi = (const float*)d_in[5];  // b
    float* out = (float*)d_out;

    agg_kernel<<<BATCH * 32 * SPLITS, THREADS>>>(cx, cy, t, sg);        // 512 blocks
    finish_kernel<<<BATCH * NOUT / OPB_B, THREADS_B>>>(W, bi, out);     // 256 blocks
}

// round 7
// speedup vs baseline: 1.1696x; 1.0292x over previous
#include <cuda_runtime.h>

namespace {

constexpr int BATCH   = 4;
constexpr int NIN     = 1024;
constexpr int NOUT    = 1024;
constexpr int CH      = 8;     // density + 7 raw channels
constexpr int OC      = 16;
constexpr int OPB     = 32;    // outputs per block (= warp width)
constexpr int SPLITS  = 4;     // i-dimension splits across blocks
constexpr int ISPB    = NIN / SPLITS;      // 256 i per block
constexpr int THREADS = 256;
constexpr int WARPS   = THREADS / 32;      // 8
constexpr int IPW     = ISPB / WARPS;      // 32 i per warp

// Partial aggregates: [b*1024+O][split][c]  (512 KB scratch)
__device__ float g_part[BATCH * NOUT * SPLITS * CH];
// Per-otile completion counters (zero-init; finisher resets -> replay-safe)
__device__ int   g_count[BATCH * 32];

__device__ __forceinline__ float ex2_approx(float x) {
    float y;
    asm("ex2.approx.f32 %0, %1;" : "=f"(y) : "f"(x));
    return y;
}

// --------- Fused kernel: partial aggregation + last-block finish ---------
__global__ __launch_bounds__(THREADS, 4)
void convdeepset_kernel(const float* __restrict__ cx,     // [B, NIN, 1]
                        const float* __restrict__ cy,     // [B, NIN, 7]
                        const float* __restrict__ t,      // [B, NOUT, 1]
                        const float* __restrict__ sigma,  // [8]
                        const float* __restrict__ W,      // [8, 16]
                        const float* __restrict__ bias,   // [16]
                        float* __restrict__ out)          // [B*NOUT, 16]
{
    __shared__ float4 sxy[ISPB][2];              // 8 KB packed {x,y1..y3},{y4..y7}
    __shared__ float  spart[WARPS][OPB][CH];     // 8 KB
    __shared__ float  sbeta[CH];
    __shared__ float  sagg2[OPB][CH];            // 1 KB (finisher only)
    __shared__ int    s_last;

    const int bi    = blockIdx.x;
    const int b     = bi >> 7;                   // / (32*4)
    const int otile = (bi >> 2) & 31;
    const int split = bi & 3;
    const int tid   = threadIdx.x;
    const int warp  = tid >> 5;
    const int lane  = tid & 31;
    const int i0    = split * ISPB;

    if (tid < CH) {
        float s = expf(sigma[tid]);
        sbeta[tid] = -0.5f * 1.4426950408889634f / (s * s);
    }

    // Stage the 256-row slice: 8 iterations per thread
    {
        float* s = reinterpret_cast<float*>(sxy);
        #pragma unroll
        for (int r = 0; r < 8; r++) {
            int idx = tid + r * THREADS;         // 0..2047
            int i = idx >> 3, c = idx & 7;
            s[idx] = (c == 0) ? cx[b * NIN + i0 + i]
                              : cy[(b * NIN + i0 + i) * 7 + (c - 1)];
        }
    }

    const float t_o = t[b * NOUT + otile * OPB + lane];
    __syncthreads();

    const float beta0 = sbeta[0];
    bool uni = true;
    #pragma unroll
    for (int c = 1; c < CH; c++) uni &= (sbeta[c] == beta0);

    float acc[CH];
    #pragma unroll
    for (int c = 0; c < CH; c++) acc[c] = 0.0f;

    const float4* row = &sxy[warp * IPW][0];

    if (uni) {
        #pragma unroll 8
        for (int j = 0; j < IPW; j++) {
            float4 p0 = row[2 * j];              // broadcast LDS.128
            float4 p1 = row[2 * j + 1];
            float d = p0.x - t_o;
            float w = ex2_approx(beta0 * (d * d));
            acc[0] += w;                         // density channel: y == 1
            acc[1] += p0.y * w;  acc[2] += p0.z * w;  acc[3] += p0.w * w;
            acc[4] += p1.x * w;  acc[5] += p1.y * w;
            acc[6] += p1.z * w;  acc[7] += p1.w * w;
        }
    } else {
        #pragma unroll 4
        for (int j = 0; j < IPW; j++) {
            float4 p0 = row[2 * j];
            float4 p1 = row[2 * j + 1];
            float d = p0.x - t_o;
            float u = d * d;
            acc[0] += ex2_approx(sbeta[0] * u);
            acc[1] += p0.y * ex2_approx(sbeta[1] * u);
            acc[2] += p0.z * ex2_approx(sbeta[2] * u);
            acc[3] += p0.w * ex2_approx(sbeta[3] * u);
            acc[4] += p1.x * ex2_approx(sbeta[4] * u);
            acc[5] += p1.y * ex2_approx(sbeta[5] * u);
            acc[6] += p1.z * ex2_approx(sbeta[6] * u);
            acc[7] += p1.w * ex2_approx(sbeta[7] * u);
        }
    }

    // Per-warp partials
    *reinterpret_cast<float4*>(&spart[warp][lane][0]) =
        make_float4(acc[0], acc[1], acc[2], acc[3]);
    *reinterpret_cast<float4*>(&spart[warp][lane][4]) =
        make_float4(acc[4], acc[5], acc[6], acc[7]);
    __syncthreads();

    // Cross-warp reduce: one thread per (o, c); write partial to scratch
    const int G0 = b * NOUT + otile * OPB;
    {
        int o = tid >> 3, c = tid & 7;
        float s = 0.0f;
        #pragma unroll
        for (int w2 = 0; w2 < WARPS; w2++) s += spart[w2][o][c];
        g_part[((G0 + o) * SPLITS + split) * CH + c] = s;
    }

    // ---- last-block-done gate (threadFenceReduction pattern) ----
    __threadfence();
    if (tid == 0) {
        int old = atomicAdd(&g_count[b * 32 + otile], 1);
        s_last = (old == SPLITS - 1);
        if (s_last) g_count[b * 32 + otile] = 0;   // reset for next replay
    }
    __syncthreads();
    if (!s_last) return;

    // ---- finish: combine splits + normalize (one thread per (o, c)) ----
    {
        int o = tid >> 3, c = tid & 7;               // 32 x 8 = 256 threads
        const float* p = &g_part[((G0 + o) * SPLITS) * CH + c];
        float s = 0.0f;
        #pragma unroll
        for (int sp = 0; sp < SPLITS; sp++) s += p[sp * CH];
        float den = __shfl_sync(0xffffffffu, s, lane & ~7u);
        sagg2[o][c] = (c == 0) ? s : s / (den + 1e-8f);
    }
    __syncthreads();

    // ---- finish: out[G][k] = bias[k] + sum_c agg2[c] * W[c][k] ----
    #pragma unroll
    for (int r = 0; r < 2; r++) {
        int idx = tid + r * THREADS;                 // 0..511
        int o = idx >> 4, k = idx & 15;
        float v = __ldg(&bias[k]);
        #pragma unroll
        for (int c = 0; c < CH; c++) v += sagg2[o][c] * __ldg(&W[c * OC + k]);
        out[(G0 + o) * OC + k] = v;                  // coalesced
    }
}

} // namespace

extern "C" void kernel_launch(void* const* d_in, const int* in_sizes, int n_in,
                              void* d_out, int out_size) {
    const float* cx = (const float*)d_in[0];  // context_x
    const float* cy = (const float*)d_in[1];  // context_y
    const float* t  = (const float*)d_in[2];  // t
    const float* sg = (const float*)d_in[3];  // sigma
    const float* W  = (const float*)d_in[4];  // W
    const float* bi = (const float*)d_in[5];  // b
    float* out = (float*)d_out;

    convdeepset_kernel<<<BATCH * 32 * SPLITS, THREADS>>>(cx, cy, t, sg, W, bi, out);
}

// round 8
// speedup vs baseline: 1.1730x; 1.0029x over previous
#include <cuda_runtime.h>

namespace {

constexpr int BATCH   = 4;
constexpr int NIN     = 1024;
constexpr int NOUT    = 1024;
constexpr int CH      = 8;     // density + 7 raw channels
constexpr int OC      = 16;
constexpr int OPB     = 32;    // outputs per block (= warp width)
constexpr int SPLITS  = 4;     // i-dimension splits across blocks
constexpr int ISPB    = NIN / SPLITS;      // 256 i per block
constexpr int THREADS = 256;
constexpr int WARPS   = THREADS / 32;      // 8
constexpr int IPW     = ISPB / WARPS;      // 32 i per warp

// Partial aggregates: [b*1024+O][split][c]  (512 KB scratch)
__device__ float g_part[BATCH * NOUT * SPLITS * CH];
// Per-otile completion counters (zero-init; finisher resets -> replay-safe)
__device__ int   g_count[BATCH * 32];

__device__ __forceinline__ float ex2_approx(float x) {
    float y;
    asm("ex2.approx.f32 %0, %1;" : "=f"(y) : "f"(x));
    return y;
}

// Packed dual-FMA: acc.{lo,hi} += y.{lo,hi} * m.{lo,hi}
__device__ __forceinline__ void ffma2(unsigned long long& acc,
                                      unsigned long long y,
                                      unsigned long long m) {
    asm("fma.rn.f32x2 %0, %1, %2, %0;" : "+l"(acc) : "l"(y), "l"(m));
}

__device__ __forceinline__ unsigned long long pack2(float w) {
    unsigned long long r;
    asm("mov.b64 %0, {%1, %1};" : "=l"(r) : "f"(w));
    return r;
}

__device__ __forceinline__ float2 unpack2(unsigned long long v) {
    float2 f;
    asm("mov.b64 {%0, %1}, %2;" : "=f"(f.x), "=f"(f.y) : "l"(v));
    return f;
}

// --------- Fused kernel: partial aggregation + last-block finish ---------
__global__ __launch_bounds__(THREADS, 4)
void convdeepset_kernel(const float* __restrict__ cx,     // [B, NIN, 1]
                        const float* __restrict__ cy,     // [B, NIN, 7]
                        const float* __restrict__ t,      // [B, NOUT, 1]
                        const float* __restrict__ sigma,  // [8]
                        const float* __restrict__ W,      // [8, 16]
                        const float* __restrict__ bias,   // [16]
                        float* __restrict__ out)          // [B*NOUT, 16]
{
    // sy[i] = [y1..y7, 1.0] -> two LDS.128 give 4 natural f32x2 pairs
    __shared__ float  sy[ISPB][CH];              // 8 KB
    __shared__ float  sx[ISPB];                  // 1 KB (pre-scaled x)
    __shared__ float  spart[WARPS][OPB][CH];     // 8 KB
    __shared__ float  sbeta[CH];
    __shared__ float  sagg2[OPB][CH];            // 1 KB (finisher only)
    __shared__ int    s_last;

    const int bi    = blockIdx.x;
    const int b     = bi >> 7;                   // / (32*4)
    const int otile = (bi >> 2) & 31;
    const int split = bi & 3;
    const int tid   = threadIdx.x;
    const int warp  = tid >> 5;
    const int lane  = tid & 31;
    const int i0    = split * ISPB;

    if (tid < CH) {
        float s = expf(sigma[tid]);
        sbeta[tid] = -0.5f * 1.4426950408889634f / (s * s);
    }

    // k = sqrt(-beta0): every thread computes (beta0 < 0 always)
    float s0 = expf(sigma[0]);
    const float kscale = sqrtf(0.5f * 1.4426950408889634f) / s0;

    // Stage y channels with density=1.0 in slot 7
    #pragma unroll
    for (int r = 0; r < 8; r++) {
        int idx = tid + r * THREADS;             // 0..2047
        int i = idx >> 3, c = idx & 7;
        sy[i][c] = (c < 7) ? cy[(b * NIN + i0 + i) * 7 + c] : 1.0f;
    }
    // Stage pre-scaled x (256 threads, 1 element each)
    sx[tid] = kscale * cx[b * NIN + i0 + tid];

    const float t_k = kscale * t[b * NOUT + otile * OPB + lane];
    __syncthreads();

    const float beta0 = sbeta[0];
    bool uni = true;
    #pragma unroll
    for (int c = 1; c < CH; c++) uni &= (sbeta[c] == beta0);

    // Canonical per-channel results: [den, y1..y7]
    float r_can[CH];

    const float*     xw = &sx[warp * IPW];
    const longlong2* yw = reinterpret_cast<const longlong2*>(&sy[warp * IPW][0]);

    if (uni) {
        unsigned long long a12 = 0, a34 = 0, a56 = 0, a7d = 0;
        #pragma unroll 8
        for (int j = 0; j < IPW; j++) {
            float d = xw[j] - t_k;               // scaled distance
            float w = ex2_approx(-(d * d));      // exp2(beta0 * d2)
            longlong2 p0 = yw[2 * j];            // {y1,y2},{y3,y4}  (broadcast)
            longlong2 p1 = yw[2 * j + 1];        // {y5,y6},{y7,1}
            unsigned long long ww = pack2(w);
            ffma2(a12, (unsigned long long)p0.x, ww);
            ffma2(a34, (unsigned long long)p0.y, ww);
            ffma2(a56, (unsigned long long)p1.x, ww);
            ffma2(a7d, (unsigned long long)p1.y, ww);
        }
        float2 u12 = unpack2(a12), u34 = unpack2(a34);
        float2 u56 = unpack2(a56), u7d = unpack2(a7d);
        r_can[0] = u7d.y;                        // density
        r_can[1] = u12.x; r_can[2] = u12.y;
        r_can[3] = u34.x; r_can[4] = u34.y;
        r_can[5] = u56.x; r_can[6] = u56.y;
        r_can[7] = u7d.x;
    } else {
        // ratios: a_c = (beta_c/beta0) * a, where a = beta0*d2
        float ratio[CH];
        #pragma unroll
        for (int c = 0; c < CH; c++) ratio[c] = sbeta[c] / beta0;
        float acc[CH];
        #pragma unroll
        for (int c = 0; c < CH; c++) acc[c] = 0.0f;
        const float* yws = &sy[warp * IPW][0];
        #pragma unroll 4
        for (int j = 0; j < IPW; j++) {
            float d = xw[j] - t_k;
            float a = -(d * d);                  // = beta0 * d2
            acc[0] += ex2_approx(ratio[0] * a);               // density
            #pragma unroll
            for (int c = 1; c < CH; c++)
                acc[c] += yws[j * CH + (c - 1)] * ex2_approx(ratio[c] * a);
        }
        #pragma unroll
        for (int c = 0; c < CH; c++) r_can[c] = acc[c];
    }

    // Per-warp partials (canonical order)
    *reinterpret_cast<float4*>(&spart[warp][lane][0]) =
        make_float4(r_can[0], r_can[1], r_can[2], r_can[3]);
    *reinterpret_cast<float4*>(&spart[warp][lane][4]) =
        make_float4(r_can[4], r_can[5], r_can[6], r_can[7]);
    __syncthreads();

    // Cross-warp reduce: one thread per (o, c); write partial to scratch
    const int G0 = b * NOUT + otile * OPB;
    {
        int o = tid >> 3, c = tid & 7;
        float s = 0.0f;
        #pragma unroll
        for (int w2 = 0; w2 < WARPS; w2++) s += spart[w2][o][c];
        g_part[((G0 + o) * SPLITS + split) * CH + c] = s;
    }

    // ---- last-block-done gate (threadFenceReduction pattern) ----
    __threadfence();
    if (tid == 0) {
        int old = atomicAdd(&g_count[b * 32 + otile], 1);
        s_last = (old == SPLITS - 1);
        if (s_last) g_count[b * 32 + otile] = 0;   // reset for next replay
    }
    __syncthreads();
    if (!s_last) return;

    // ---- finish: combine splits + normalize (one thread per (o, c)) ----
    {
        int o = tid >> 3, c = tid & 7;               // 32 x 8 = 256 threads
        const float* p = &g_part[((G0 + o) * SPLITS) * CH + c];
        float s = 0.0f;
        #pragma unroll
        for (int sp = 0; sp < SPLITS; sp++) s += p[sp * CH];
        float den = __shfl_sync(0xffffffffu, s, lane & ~7u);
        sagg2[o][c] = (c == 0) ? s : s / (den + 1e-8f);
    }
    __syncthreads();

    // ---- finish: out[G][k] = bias[k] + sum_c agg2[c] * W[c][k] ----
    #pragma unroll
    for (int r = 0; r < 2; r++) {
        int idx = tid + r * THREADS;                 // 0..511
        int o = idx >> 4, k = idx & 15;
        float v = __ldg(&bias[k]);
        #pragma unroll
        for (int c = 0; c < CH; c++) v += sagg2[o][c] * __ldg(&W[c * OC + k]);
        out[(G0 + o) * OC + k] = v;                  // coalesced
    }
}

} // namespace

extern "C" void kernel_launch(void* const* d_in, const int* in_sizes, int n_in,
                              void* d_out, int out_size) {
    const float* cx = (const float*)d_in[0];  // context_x
    const float* cy = (const float*)d_in[1];  // context_y
    const float* t  = (const float*)d_in[2];  // t
    const float* sg = (const float*)d_in[3];  // sigma
    const float* W  = (const float*)d_in[4];  // W
    const float* bi = (const float*)d_in[5];  // b
    float* out = (float*)d_out;

    convdeepset_kernel<<<BATCH * 32 * SPLITS, THREADS>>>(cx, cy, t, sg, W, bi, out);
}